// round 14
// baseline (speedup 1.0000x reference)
#include <cuda_runtime.h>
#include <stdint.h>
#include <math.h>

#define BB 128
#define AA 8732
#define CC 21
#define MM 8
#define TT 1024
#define NW (TT / 32)                     // 32 warps
#define NT ((AA + TT - 1) / TT)          // 9 tiles
#define TILE_F4 (TT * CC / 4)            // 5376 float4 per full tile
#define TILE_B  (TT * CC * 4)            // 86016 B per tile

// dynamic smem layout
#define OFF_VAL  0                        // float s_val[8732]  (iou -> ce)
#define OFF_CLS  34928                    // uchar s_obj[8732] pad 8736
#define OFF_BUF  43664                    // 2 tile buffers
#define SMEM_TOTAL (OFF_BUF + 2 * TILE_B) // 215696 B

// per-image partials (fully overwritten every launch) + self-resetting ticket
__device__ float g_pos[BB], g_hard[BB], g_loc[BB];
__device__ int   g_np[BB];
__device__ int   g_ctr = 0;

__device__ __forceinline__ void cp16_pred(unsigned int dst, const void* src, int ok) {
    asm volatile("{\n\t.reg .pred p;\n\tsetp.ne.s32 p, %2, 0;\n\t"
                 "@p cp.async.cg.shared.global [%0], [%1], 16;\n\t}"
                 :: "r"(dst), "l"(src), "r"(ok));
}
#define CP_COMMIT() asm volatile("cp.async.commit_group;" ::: "memory")
#define CP_WAIT1()  asm volatile("cp.async.wait_group 1;" ::: "memory")

__global__ void __launch_bounds__(TT, 1) k_fused(
    const float* __restrict__ locs,
    const float* __restrict__ scores,
    const float* __restrict__ boxes,
    const int*   __restrict__ labels,
    const float* __restrict__ anchors,
    float* __restrict__ out)
{
    extern __shared__ char dsm[];
    float*         s_val = (float*)dsm;                       // iou -> ce
    unsigned char* s_obj = (unsigned char*)(dsm + OFF_CLS);   // obj -> cls

    __shared__ float4 s_bx4[MM];
    __shared__ float4 s_raw4[MM];
    __shared__ float  s_area[MM];
    __shared__ int    s_lab[MM];
    __shared__ float  s_wv[NW][MM];
    __shared__ int    s_wi[NW][MM];
    __shared__ int    s_afo[MM];
    __shared__ float  s_redf[NW];
    __shared__ float  s_redf2[NW];
    __shared__ int    s_redi[NW];
    __shared__ unsigned s_cnt[2][NW];
    __shared__ int    s_npos;
    __shared__ float  s_lsum, s_cpos;
    __shared__ int    s_bin1;  __shared__ unsigned s_chi;
    __shared__ unsigned s_prefix;
    __shared__ int    s_ticket;

    const int b = blockIdx.x, tid = threadIdx.x;
    const int lane = tid & 31, wid = tid >> 5;
    const float4* anc4 = (const float4*)anchors;
    const float4* sc4  = (const float4*)(scores + (size_t)b * AA * CC);

    // ---- prefetch tiles 0 & 1 (172 KB) — drains during phase A ----
#pragma unroll
    for (int t = 0; t < 2; t++) {
        int rows = AA - t * TT; if (rows > TT) rows = TT;
        int n4 = (rows * CC) >> 2;
        const float4* src = sc4 + (size_t)t * TILE_F4;
        unsigned int dbase = (unsigned int)__cvta_generic_to_shared(dsm + OFF_BUF + t * TILE_B);
#pragma unroll
        for (int j = 0; j < 6; j++) {
            int i = tid + j * TT;
            int ok = i < n4;
            cp16_pred(ok ? (dbase + i * 16) : dbase,
                      ok ? (const void*)(src + i) : (const void*)sc4, ok);
        }
        CP_COMMIT();
    }

    // ---- setup ----
    if (tid < MM) {
        int m = tid;
        float x1 = boxes[(b * MM + m) * 4 + 0];
        float y1 = boxes[(b * MM + m) * 4 + 1];
        float x2 = boxes[(b * MM + m) * 4 + 2];
        float y2 = boxes[(b * MM + m) * 4 + 3];
        s_raw4[m] = make_float4(x1, y1, x2, y2);
        float sx1 = x1 / 300.f, sy1 = y1 / 300.f, sx2 = x2 / 300.f, sy2 = y2 / 300.f;
        s_bx4[m] = make_float4(sx1, sy1, sx2, sy2);
        s_area[m] = (sx2 - sx1) * (sy2 - sy1);
        s_lab[m]  = labels[b * MM + m];
    }
    __syncthreads();

    // ---- phase A: IoU matching ----
    {
        float bestv[MM]; int besti[MM];
#pragma unroll
        for (int m = 0; m < MM; m++) { bestv[m] = -1.f; besti[m] = 0; }

        for (int a = tid; a < AA; a += TT) {
            float4 an = anc4[a];
            float ax1 = fmaf(an.z, -0.5f, an.x), ay1 = fmaf(an.w, -0.5f, an.y);
            float ax2 = fmaf(an.z,  0.5f, an.x), ay2 = fmaf(an.w,  0.5f, an.y);
            float areaA = (ax2 - ax1) * (ay2 - ay1);
            float bmv = -1.f; int bmi = 0;
#pragma unroll
            for (int m = 0; m < MM; m++) {
                float4 bx = s_bx4[m];
                float lx = fmaxf(bx.x, ax1);
                float ly = fmaxf(bx.y, ay1);
                float rx = fminf(bx.z, ax2);
                float ry = fminf(bx.w, ay2);
                float iw = fmaxf(rx - lx, 0.f), ih = fmaxf(ry - ly, 0.f);
                float inter = iw * ih;
                float iou = __fdividef(inter, s_area[m] + areaA - inter);
                if (iou > bmv) { bmv = iou; bmi = m; }        // first-index tie-break
                if (iou > bestv[m]) { bestv[m] = iou; besti[m] = a; }
            }
            s_val[a] = bmv;
            s_obj[a] = (unsigned char)bmi;
        }

#pragma unroll
        for (int m = 0; m < MM; m++) {
            float v = bestv[m]; int i = besti[m];
            for (int off = 16; off; off >>= 1) {
                float ov = __shfl_down_sync(0xffffffffu, v, off);
                int   oi = __shfl_down_sync(0xffffffffu, i, off);
                if (ov > v || (ov == v && oi < i)) { v = ov; i = oi; }
            }
            if (lane == 0) { s_wv[wid][m] = v; s_wi[wid][m] = i; }
        }
        __syncthreads();
        if (tid < MM) {
            int m = tid;
            float v = s_wv[0][m]; int i = s_wi[0][m];
            for (int w2 = 1; w2 < NW; w2++) {
                float ov = s_wv[w2][m]; int oi = s_wi[w2][m];
                if (ov > v || (ov == v && oi < i)) { v = ov; i = oi; }
            }
            s_afo[m] = i;
        }
        __syncthreads();
        if (tid == 0) {       // sequential last-wins scatter override
            for (int m = 0; m < MM; m++) {
                int a = s_afo[m];
                s_obj[a] = (unsigned char)m;
                s_val[a] = 1.0f;
            }
        }
        __syncthreads();
    }

    // ---- phase B: labels + positive L1 loc loss ----
    {
        int npos = 0; float lsum = 0.f;
        const float4* locs4 = (const float4*)locs + (size_t)b * AA;
        for (int a = tid; a < AA; a += TT) {
            float iou = s_val[a];
            int   m   = s_obj[a];
            int   cls = (iou < 0.5f) ? 0 : s_lab[m];
            s_obj[a] = (unsigned char)cls;    // in-place obj -> cls
            if (cls != 0) {
                npos++;
                float4 an = anc4[a];
                float4 rw = s_raw4[m];
                float t0 = (rw.x - an.x) * __fdividef(10.f, an.z);
                float t1 = (rw.y - an.y) * __fdividef(10.f, an.w);
                float t2 = __logf(__fdividef(rw.z, an.z)) * 5.f;
                float t3 = __logf(__fdividef(rw.w, an.w)) * 5.f;
                float4 p = locs4[a];
                lsum += fabsf(p.x - t0) + fabsf(p.y - t1) + fabsf(p.z - t2) + fabsf(p.w - t3);
            }
        }
        for (int off = 16; off; off >>= 1) {
            npos += __shfl_xor_sync(0xffffffffu, npos, off);
            lsum += __shfl_xor_sync(0xffffffffu, lsum, off);
        }
        if (lane == 0) { s_redf[wid] = lsum; s_redi[wid] = npos; }
        __syncthreads();
        if (tid == 0) {
            float L = 0.f; int N = 0;
            for (int w2 = 0; w2 < NW; w2++) { L += s_redf[w2]; N += s_redi[w2]; }
            s_npos = N; s_lsum = L;
        }
        __syncthreads();
    }

    // ---- phase C: CE, double-buffered cp.async pipeline, no max-subtraction ----
    {
        float cpos = 0.f;
        for (int t = 0; t < NT; t++) {
            CP_WAIT1();
            __syncthreads();
            const float* buf = (const float*)(dsm + OFF_BUF + (t & 1) * TILE_B);
            int rows = AA - t * TT; if (rows > TT) rows = TT;
            if (tid < rows) {
                int row = t * TT + tid;
                const float* x = buf + tid * CC;     // stride 21: conflict-free
                float s0 = 0.f, s1 = 0.f, s2 = 0.f;
#pragma unroll
                for (int c = 0; c < CC; c += 3) {
                    s0 += __expf(x[c]);
                    if (c + 1 < CC) s1 += __expf(x[c + 1]);
                    if (c + 2 < CC) s2 += __expf(x[c + 2]);
                }
                float lse = __logf(s0 + s1 + s2);
                int cls = s_obj[row];
                float ce = lse - x[cls];
                if (cls != 0) { cpos += ce; s_val[row] = 0.f; }
                else          s_val[row] = ce;
            }
            __syncthreads();
            int tn = t + 2;
            if (tn < NT) {
                int rows2 = AA - tn * TT; if (rows2 > TT) rows2 = TT;
                int n4 = (rows2 * CC) >> 2;
                const float4* src = sc4 + (size_t)tn * TILE_F4;
                unsigned int dbase = (unsigned int)__cvta_generic_to_shared(
                    dsm + OFF_BUF + (t & 1) * TILE_B);
#pragma unroll
                for (int j = 0; j < 6; j++) {
                    int i = tid + j * TT;
                    int ok = i < n4;
                    cp16_pred(ok ? (dbase + i * 16) : dbase,
                              ok ? (const void*)(src + i) : (const void*)sc4, ok);
                }
            }
            CP_COMMIT();
        }
        for (int off = 16; off; off >>= 1)
            cpos += __shfl_xor_sync(0xffffffffu, cpos, off);
        if (lane == 0) s_redf[wid] = cpos;
        __syncthreads();
        if (tid == 0) {
            float P = 0.f;
            for (int w2 = 0; w2 < NW; w2++) P += s_redf[w2];
            s_cpos = P;
        }
        __syncthreads();
    }

    // ---- phase D: top-k sum via 2-level histogram radix select ----
    {
        unsigned k = (unsigned)(3 * s_npos); if (k > AA) k = AA;
        unsigned* hist = (unsigned*)(dsm + OFF_BUF);   // reuse tile buffer

        // pass 1: 2048 bins on bits [31:20), warp-aggregated atomics
        // (negatives' ce values cluster into few exponent bins)
        for (int i = tid; i < 2048; i += TT) hist[i] = 0u;
        __syncthreads();
        for (int i = tid; i < AA; i += TT) {
            unsigned bin = __float_as_uint(s_val[i]) >> 20;
            unsigned mask  = __activemask();
            unsigned peers = __match_any_sync(mask, bin);
            int leader = __ffs(peers) - 1;
            if (lane == leader) atomicAdd(&hist[bin], (unsigned)__popc(peers));
        }
        __syncthreads();
        {
            int base = tid * 2;                      // 2 bins per thread
            unsigned h0 = hist[base], h1 = hist[base + 1];
            unsigned loc = h0 + h1;
            unsigned inc = loc;
            for (int off = 1; off < 32; off <<= 1) {
                unsigned o = __shfl_down_sync(0xffffffffu, inc, off);
                if (lane < 32 - off) inc += o;
            }
            if (lane == 0) s_cnt[0][wid] = inc;
            __syncthreads();
            if (tid == 0) {
                unsigned c = 0;
                for (int w = NW - 1; w >= 0; --w) { s_cnt[1][w] = c; c += s_cnt[0][w]; }
            }
            __syncthreads();
            unsigned suf = s_cnt[1][wid] + (inc - loc);   // count in bins above mine
            if (suf < k && suf + loc >= k) {
                if (suf + h1 >= k) { s_bin1 = base + 1; s_chi = suf; }
                else               { s_bin1 = base;     s_chi = suf + h1; }
            }
        }
        __syncthreads();
        unsigned bin1 = (unsigned)s_bin1, chi = s_chi, k2 = k - chi;

        // pass 2: 4096 bins on bits [20:8) among values with top bits == bin1
        for (int i = tid; i < 4096; i += TT) hist[i] = 0u;
        __syncthreads();
        for (int i = tid; i < AA; i += TT) {
            unsigned u = __float_as_uint(s_val[i]);
            if ((u >> 20) == bin1) atomicAdd(&hist[(u >> 8) & 0xFFFu], 1u);
        }
        __syncthreads();
        {
            int base = tid * 4;                      // 4 bins per thread
            unsigned h[4]; unsigned loc = 0;
#pragma unroll
            for (int j = 0; j < 4; j++) { h[j] = hist[base + j]; loc += h[j]; }
            unsigned inc = loc;
            for (int off = 1; off < 32; off <<= 1) {
                unsigned o = __shfl_down_sync(0xffffffffu, inc, off);
                if (lane < 32 - off) inc += o;
            }
            if (lane == 0) s_cnt[0][wid] = inc;
            __syncthreads();
            if (tid == 0) {
                unsigned c = 0;
                for (int w = NW - 1; w >= 0; --w) { s_cnt[1][w] = c; c += s_cnt[0][w]; }
            }
            __syncthreads();
            unsigned suf = s_cnt[1][wid] + (inc - loc);
            if (suf < k2 && suf + loc >= k2) {
                unsigned c = suf; int bin2 = base;
#pragma unroll
                for (int j = 3; j >= 0; --j) {
                    if (c + h[j] >= k2) { bin2 = base + j; break; }
                    c += h[j];
                }
                s_prefix = (bin1 << 20) | ((unsigned)bin2 << 8);
            }
        }
        __syncthreads();
        unsigned prefix = s_prefix;
        float kth = __uint_as_float(prefix);

        int cgt = 0; float sgt = 0.f;
        for (int i = tid; i < AA; i += TT) {
            float v = s_val[i];
            if (__float_as_uint(v) > prefix) { cgt++; sgt += v; }
        }
        for (int off = 16; off; off >>= 1) {
            cgt += __shfl_xor_sync(0xffffffffu, cgt, off);
            sgt += __shfl_xor_sync(0xffffffffu, sgt, off);
        }
        __syncthreads();
        if (lane == 0) { s_redi[wid] = cgt; s_redf[wid] = sgt; }
        __syncthreads();
        if (tid == 0) {
            int Cg = 0; float S = 0.f;
            for (int w2 = 0; w2 < NW; w2++) { Cg += s_redi[w2]; S += s_redf[w2]; }
            S += (float)((int)k - Cg) * kth;
            g_hard[b] = S;
            g_pos[b]  = s_cpos;
            g_loc[b]  = s_lsum;
            g_np[b]   = s_npos;
        }
    }

    // ---- phase E: last CTA reduces all per-image partials ----
    __threadfence();
    if (tid == 0) s_ticket = atomicAdd(&g_ctr, 1);
    __syncthreads();
    if (s_ticket == BB - 1) {
        __threadfence();
        if (tid == 0) g_ctr = 0;           // self-reset for next graph replay
        float p = 0.f, h = 0.f, l = 0.f; int n = 0;
        if (tid < BB) { p = g_pos[tid]; h = g_hard[tid]; l = g_loc[tid]; n = g_np[tid]; }
        for (int off = 16; off; off >>= 1) {
            p += __shfl_xor_sync(0xffffffffu, p, off);
            h += __shfl_xor_sync(0xffffffffu, h, off);
            l += __shfl_xor_sync(0xffffffffu, l, off);
            n += __shfl_xor_sync(0xffffffffu, n, off);
        }
        if (lane == 0) { s_redf[wid] = p + h; s_redf2[wid] = l; s_redi[wid] = n; }
        __syncthreads();
        if (tid == 0) {
            float PH = 0.f, L = 0.f; int N = 0;
            for (int w = 0; w < NW; w++) { PH += s_redf[w]; L += s_redf2[w]; N += s_redi[w]; }
            float np = (float)N;
            out[0] = PH / np + L / (np * 4.f);
        }
    }
}

extern "C" void kernel_launch(void* const* d_in, const int* in_sizes, int n_in,
                              void* d_out, int out_size) {
    const float* locs    = (const float*)d_in[0];
    const float* scores  = (const float*)d_in[1];
    const float* boxes   = (const float*)d_in[2];
    const int*   labels  = (const int*)d_in[3];
    const float* anchors = (const float*)d_in[4];
    float* out = (float*)d_out;

    cudaFuncSetAttribute(k_fused, cudaFuncAttributeMaxDynamicSharedMemorySize, SMEM_TOTAL);
    k_fused<<<BB, TT, SMEM_TOTAL>>>(locs, scores, boxes, labels, anchors, out);
}

// round 15
// speedup vs baseline: 1.1445x; 1.1445x over previous
#include <cuda_runtime.h>
#include <stdint.h>
#include <math.h>

#define BB 128
#define AA 8732
#define CC 21
#define MM 8
#define TT 512
#define NW (TT / 32)
#define CE_T 256                          // CE group threads (warps 0-7)
#define TROWS 512                         // rows per tile
#define NT 18                             // ceil(8732/512)
#define TILE_F4 (TROWS * CC / 4)          // 2688 float4 per full tile
#define TILE_B  (TROWS * CC * 4)          // 43008 B

// dynamic smem layout
#define OFF_VAL  0                        // float s_val[8732]  (ce0)
#define OFF_IOU  34928                    // float s_iou[8732]
#define OFF_CLS  69856                    // uchar s_obj[8732] pad 8736
#define OFF_BUF  78592                    // 3 tile buffers
#define SMEM_TOTAL (OFF_BUF + 3 * TILE_B) // 207616 B

__device__ float g_pos[BB], g_hard[BB], g_loc[BB];
__device__ int   g_np[BB];
__device__ int   g_ctr = 0;

__device__ __forceinline__ void cp16_pred(unsigned int dst, const void* src, int ok) {
    asm volatile("{\n\t.reg .pred p;\n\tsetp.ne.s32 p, %2, 0;\n\t"
                 "@p cp.async.cg.shared.global [%0], [%1], 16;\n\t}"
                 :: "r"(dst), "l"(src), "r"(ok));
}
#define CP_COMMIT() asm volatile("cp.async.commit_group;" ::: "memory")
#define CP_WAIT2()  asm volatile("cp.async.wait_group 2;" ::: "memory")
#define BAR_CE()    asm volatile("bar.sync 1, 256;" ::: "memory")
#define BAR_MT()    asm volatile("bar.sync 2, 256;" ::: "memory")

__global__ void __launch_bounds__(TT, 1) k_fused(
    const float* __restrict__ locs,
    const float* __restrict__ scores,
    const float* __restrict__ boxes,
    const int*   __restrict__ labels,
    const float* __restrict__ anchors,
    float* __restrict__ out)
{
    extern __shared__ char dsm[];
    float*         s_val = (float*)dsm;                       // ce0 per anchor
    float*         s_iou = (float*)(dsm + OFF_IOU);
    unsigned char* s_obj = (unsigned char*)(dsm + OFF_CLS);   // obj -> cls

    __shared__ float4 s_bx4[MM];
    __shared__ float4 s_raw4[MM];
    __shared__ float  s_area[MM];
    __shared__ int    s_lab[MM];
    __shared__ float  s_wv[8][MM];
    __shared__ int    s_wi[8][MM];
    __shared__ int    s_afo[MM];
    __shared__ float  s_redf[NW];
    __shared__ float  s_redf2[NW];
    __shared__ int    s_redi[NW];
    __shared__ unsigned s_cnt[2][NW];
    __shared__ int    s_npos;
    __shared__ float  s_lsum, s_cpos;
    __shared__ int    s_bin1;  __shared__ unsigned s_chi;
    __shared__ unsigned s_prefix;
    __shared__ int    s_ticket;

    const int b = blockIdx.x, tid = threadIdx.x;
    const int lane = tid & 31, wid = tid >> 5;
    const float4* anc4 = (const float4*)anchors;
    const float*  scb  = scores + (size_t)b * AA * CC;
    const float4* sc4  = (const float4*)scb;

    if (tid < CE_T) {
        // ================== CE streaming group (warps 0-7) ==================
        const int ctid = tid;
        // prefetch tiles 0..2 into the 3-buffer ring
#pragma unroll
        for (int t = 0; t < 3; t++) {
            int rows = AA - t * TROWS; if (rows > TROWS) rows = TROWS;
            int n4 = (rows * CC) >> 2;
            const float4* src = sc4 + (size_t)t * TILE_F4;
            unsigned int dbase = (unsigned int)__cvta_generic_to_shared(dsm + OFF_BUF + t * TILE_B);
#pragma unroll
            for (int j = 0; j < 11; j++) {
                int i = ctid + j * CE_T;
                int ok = i < n4;
                cp16_pred(ok ? (dbase + i * 16) : dbase,
                          ok ? (const void*)(src + i) : (const void*)sc4, ok);
            }
            CP_COMMIT();
        }
        for (int t = 0; t < NT; t++) {
            CP_WAIT2();
            BAR_CE();                           // tile t data visible to all CE threads
            const float* buf = (const float*)(dsm + OFF_BUF + (t % 3) * TILE_B);
            int rows = AA - t * TROWS; if (rows > TROWS) rows = TROWS;
#pragma unroll
            for (int h = 0; h < 2; h++) {
                int r = ctid + h * CE_T;
                if (r < rows) {
                    const float* x = buf + r * CC;          // stride 21: conflict-free
                    float s0 = 0.f, s1 = 0.f, s2 = 0.f;
#pragma unroll
                    for (int c = 0; c < CC; c += 3) {
                        s0 += __expf(x[c]);
                        if (c + 1 < CC) s1 += __expf(x[c + 1]);
                        if (c + 2 < CC) s2 += __expf(x[c + 2]);
                    }
                    // ce0 = lse - x[0]  (class-independent; positives fixed later)
                    s_val[t * TROWS + r] = __logf(s0 + s1 + s2) - x[0];
                }
            }
            BAR_CE();                           // all reads of buffer (t%3) done
            int tn = t + 3;
            if (tn < NT) {
                int rows2 = AA - tn * TROWS; if (rows2 > TROWS) rows2 = TROWS;
                int n4 = (rows2 * CC) >> 2;
                const float4* src = sc4 + (size_t)tn * TILE_F4;
                unsigned int dbase = (unsigned int)__cvta_generic_to_shared(
                    dsm + OFF_BUF + (tn % 3) * TILE_B);
#pragma unroll
                for (int j = 0; j < 11; j++) {
                    int i = ctid + j * CE_T;
                    int ok = i < n4;
                    cp16_pred(ok ? (dbase + i * 16) : dbase,
                              ok ? (const void*)(src + i) : (const void*)sc4, ok);
                }
            }
            CP_COMMIT();                        // empty group ok on tail iters
        }
    } else {
        // ================== matching group (warps 8-15) ==================
        const int mtid = tid - CE_T;            // 0..255
        const int mwid = mtid >> 5;             // 0..7
        if (mtid < MM) {
            int m = mtid;
            float x1 = boxes[(b * MM + m) * 4 + 0];
            float y1 = boxes[(b * MM + m) * 4 + 1];
            float x2 = boxes[(b * MM + m) * 4 + 2];
            float y2 = boxes[(b * MM + m) * 4 + 3];
            s_raw4[m] = make_float4(x1, y1, x2, y2);
            float sx1 = x1 / 300.f, sy1 = y1 / 300.f, sx2 = x2 / 300.f, sy2 = y2 / 300.f;
            s_bx4[m] = make_float4(sx1, sy1, sx2, sy2);
            s_area[m] = (sx2 - sx1) * (sy2 - sy1);
            s_lab[m]  = labels[b * MM + m];
        }
        BAR_MT();

        float bestv[MM]; int besti[MM];
#pragma unroll
        for (int m = 0; m < MM; m++) { bestv[m] = -1.f; besti[m] = 0; }

        for (int a = mtid; a < AA; a += CE_T) {
            float4 an = anc4[a];
            float ax1 = fmaf(an.z, -0.5f, an.x), ay1 = fmaf(an.w, -0.5f, an.y);
            float ax2 = fmaf(an.z,  0.5f, an.x), ay2 = fmaf(an.w,  0.5f, an.y);
            float areaA = (ax2 - ax1) * (ay2 - ay1);
            float bmv = -1.f; int bmi = 0;
#pragma unroll
            for (int m = 0; m < MM; m++) {
                float4 bx = s_bx4[m];
                float lx = fmaxf(bx.x, ax1);
                float ly = fmaxf(bx.y, ay1);
                float rx = fminf(bx.z, ax2);
                float ry = fminf(bx.w, ay2);
                float iw = fmaxf(rx - lx, 0.f), ih = fmaxf(ry - ly, 0.f);
                float inter = iw * ih;
                float iou = __fdividef(inter, s_area[m] + areaA - inter);
                if (iou > bmv) { bmv = iou; bmi = m; }        // first-index tie-break
                if (iou > bestv[m]) { bestv[m] = iou; besti[m] = a; }
            }
            s_iou[a] = bmv;
            s_obj[a] = (unsigned char)bmi;
        }

#pragma unroll
        for (int m = 0; m < MM; m++) {
            float v = bestv[m]; int i = besti[m];
            for (int off = 16; off; off >>= 1) {
                float ov = __shfl_down_sync(0xffffffffu, v, off);
                int   oi = __shfl_down_sync(0xffffffffu, i, off);
                if (ov > v || (ov == v && oi < i)) { v = ov; i = oi; }
            }
            if (lane == 0) { s_wv[mwid][m] = v; s_wi[mwid][m] = i; }
        }
        BAR_MT();
        if (mtid < MM) {
            int m = mtid;
            float v = s_wv[0][m]; int i = s_wi[0][m];
            for (int w2 = 1; w2 < 8; w2++) {
                float ov = s_wv[w2][m]; int oi = s_wi[w2][m];
                if (ov > v || (ov == v && oi < i)) { v = ov; i = oi; }
            }
            s_afo[m] = i;
        }
        BAR_MT();
        if (mtid == 0) {       // sequential last-wins scatter override
            for (int m = 0; m < MM; m++) {
                int a = s_afo[m];
                s_obj[a] = (unsigned char)m;
                s_iou[a] = 1.0f;
            }
        }
    }

    __syncthreads();   // join: s_val (ce0), s_iou, s_obj all complete

    // ---- phase B: labels + loc loss + positive-CE fixup (all 512 threads) ----
    {
        int npos = 0; float lsum = 0.f, cpos = 0.f;
        const float4* locs4 = (const float4*)locs + (size_t)b * AA;
        for (int a = tid; a < AA; a += TT) {
            float iou = s_iou[a];
            int   m   = s_obj[a];
            int   cls = (iou < 0.5f) ? 0 : s_lab[m];
            s_obj[a] = (unsigned char)cls;
            if (cls != 0) {
                npos++;
                float4 an = anc4[a];
                float4 rw = s_raw4[m];
                float t0 = (rw.x - an.x) * __fdividef(10.f, an.z);
                float t1 = (rw.y - an.y) * __fdividef(10.f, an.w);
                float t2 = __logf(__fdividef(rw.z, an.z)) * 5.f;
                float t3 = __logf(__fdividef(rw.w, an.w)) * 5.f;
                float4 p = locs4[a];
                lsum += fabsf(p.x - t0) + fabsf(p.y - t1) + fabsf(p.z - t2) + fabsf(p.w - t3);
                // CE fixup: ce = ce0 + x[0] - x[cls]
                float x0 = scb[(size_t)a * CC];
                float xc = scb[(size_t)a * CC + cls];
                cpos += s_val[a] + x0 - xc;
                s_val[a] = 0.f;
            }
        }
        for (int off = 16; off; off >>= 1) {
            npos += __shfl_xor_sync(0xffffffffu, npos, off);
            lsum += __shfl_xor_sync(0xffffffffu, lsum, off);
            cpos += __shfl_xor_sync(0xffffffffu, cpos, off);
        }
        if (lane == 0) { s_redf[wid] = lsum; s_redf2[wid] = cpos; s_redi[wid] = npos; }
        __syncthreads();
        if (tid == 0) {
            float L = 0.f, P = 0.f; int N = 0;
            for (int w2 = 0; w2 < NW; w2++) { L += s_redf[w2]; P += s_redf2[w2]; N += s_redi[w2]; }
            s_npos = N; s_lsum = L; s_cpos = P;
        }
        __syncthreads();
    }

    // ---- phase D: top-k sum via 2-level histogram radix select ----
    {
        unsigned k = (unsigned)(3 * s_npos); if (k > AA) k = AA;
        unsigned* hist = (unsigned*)(dsm + OFF_BUF);   // reuse tile buffer

        // pass 1: 2048 bins on bits [31:20), warp-aggregated atomics
        for (int i = tid; i < 2048; i += TT) hist[i] = 0u;
        __syncthreads();
        for (int i = tid; i < AA; i += TT) {
            unsigned bin = __float_as_uint(s_val[i]) >> 20;
            unsigned mask  = __activemask();
            unsigned peers = __match_any_sync(mask, bin);
            int leader = __ffs(peers) - 1;
            if (lane == leader) atomicAdd(&hist[bin], (unsigned)__popc(peers));
        }
        __syncthreads();
        {
            int base = tid * 4;
            unsigned h0 = hist[base], h1 = hist[base + 1], h2 = hist[base + 2], h3 = hist[base + 3];
            unsigned loc = h0 + h1 + h2 + h3;
            unsigned inc = loc;
            for (int off = 1; off < 32; off <<= 1) {
                unsigned o = __shfl_down_sync(0xffffffffu, inc, off);
                if (lane < 32 - off) inc += o;
            }
            if (lane == 0) s_cnt[0][wid] = inc;
            __syncthreads();
            if (tid == 0) {
                unsigned c = 0;
                for (int w = NW - 1; w >= 0; --w) { s_cnt[1][w] = c; c += s_cnt[0][w]; }
            }
            __syncthreads();
            unsigned suf = s_cnt[1][wid] + (inc - loc);
            if (suf < k && suf + loc >= k) {
                unsigned c = suf;
                if      (c + h3 >= k) { s_bin1 = base + 3; s_chi = c; }
                else if (c + h3 + h2 >= k) { s_bin1 = base + 2; s_chi = c + h3; }
                else if (c + h3 + h2 + h1 >= k) { s_bin1 = base + 1; s_chi = c + h3 + h2; }
                else { s_bin1 = base; s_chi = c + h3 + h2 + h1; }
            }
        }
        __syncthreads();
        unsigned bin1 = (unsigned)s_bin1, chi = s_chi, k2 = k - chi;

        // pass 2: 4096 bins on bits [20:8)
        for (int i = tid; i < 4096; i += TT) hist[i] = 0u;
        __syncthreads();
        for (int i = tid; i < AA; i += TT) {
            unsigned u = __float_as_uint(s_val[i]);
            if ((u >> 20) == bin1) atomicAdd(&hist[(u >> 8) & 0xFFFu], 1u);
        }
        __syncthreads();
        {
            int base = tid * 8;
            unsigned h[8]; unsigned loc = 0;
#pragma unroll
            for (int j = 0; j < 8; j++) { h[j] = hist[base + j]; loc += h[j]; }
            unsigned inc = loc;
            for (int off = 1; off < 32; off <<= 1) {
                unsigned o = __shfl_down_sync(0xffffffffu, inc, off);
                if (lane < 32 - off) inc += o;
            }
            if (lane == 0) s_cnt[0][wid] = inc;
            __syncthreads();
            if (tid == 0) {
                unsigned c = 0;
                for (int w = NW - 1; w >= 0; --w) { s_cnt[1][w] = c; c += s_cnt[0][w]; }
            }
            __syncthreads();
            unsigned suf = s_cnt[1][wid] + (inc - loc);
            if (suf < k2 && suf + loc >= k2) {
                unsigned c = suf; int bin2 = base;
#pragma unroll
                for (int j = 7; j >= 0; --j) {
                    if (c + h[j] >= k2) { bin2 = base + j; break; }
                    c += h[j];
                }
                s_prefix = (bin1 << 20) | ((unsigned)bin2 << 8);
            }
        }
        __syncthreads();
        unsigned prefix = s_prefix;
        float kth = __uint_as_float(prefix);

        int cgt = 0; float sgt = 0.f;
        for (int i = tid; i < AA; i += TT) {
            float v = s_val[i];
            if (__float_as_uint(v) > prefix) { cgt++; sgt += v; }
        }
        for (int off = 16; off; off >>= 1) {
            cgt += __shfl_xor_sync(0xffffffffu, cgt, off);
            sgt += __shfl_xor_sync(0xffffffffu, sgt, off);
        }
        __syncthreads();
        if (lane == 0) { s_redi[wid] = cgt; s_redf[wid] = sgt; }
        __syncthreads();
        if (tid == 0) {
            int Cg = 0; float S = 0.f;
            for (int w2 = 0; w2 < NW; w2++) { Cg += s_redi[w2]; S += s_redf[w2]; }
            S += (float)((int)k - Cg) * kth;
            g_hard[b] = S;
            g_pos[b]  = s_cpos;
            g_loc[b]  = s_lsum;
            g_np[b]   = s_npos;
        }
    }

    // ---- phase E: last CTA reduces all per-image partials ----
    __threadfence();
    if (tid == 0) s_ticket = atomicAdd(&g_ctr, 1);
    __syncthreads();
    if (s_ticket == BB - 1) {
        __threadfence();
        if (tid == 0) g_ctr = 0;           // self-reset for next graph replay
        float p = 0.f, h = 0.f, l = 0.f; int n = 0;
        if (tid < BB) { p = g_pos[tid]; h = g_hard[tid]; l = g_loc[tid]; n = g_np[tid]; }
        for (int off = 16; off; off >>= 1) {
            p += __shfl_xor_sync(0xffffffffu, p, off);
            h += __shfl_xor_sync(0xffffffffu, h, off);
            l += __shfl_xor_sync(0xffffffffu, l, off);
            n += __shfl_xor_sync(0xffffffffu, n, off);
        }
        if (lane == 0) { s_redf[wid] = p + h; s_redf2[wid] = l; s_redi[wid] = n; }
        __syncthreads();
        if (tid == 0) {
            float PH = 0.f, L = 0.f; int N = 0;
            for (int w = 0; w < NW; w++) { PH += s_redf[w]; L += s_redf2[w]; N += s_redi[w]; }
            float np = (float)N;
            out[0] = PH / np + L / (np * 4.f);
        }
    }
}

extern "C" void kernel_launch(void* const* d_in, const int* in_sizes, int n_in,
                              void* d_out, int out_size) {
    const float* locs    = (const float*)d_in[0];
    const float* scores  = (const float*)d_in[1];
    const float* boxes   = (const float*)d_in[2];
    const int*   labels  = (const int*)d_in[3];
    const float* anchors = (const float*)d_in[4];
    float* out = (float*)d_out;

    cudaFuncSetAttribute(k_fused, cudaFuncAttributeMaxDynamicSharedMemorySize, SMEM_TOTAL);
    k_fused<<<BB, TT, SMEM_TOTAL>>>(locs, scores, boxes, labels, anchors, out);
}

// round 17
// speedup vs baseline: 1.1461x; 1.0014x over previous
#include <cuda_runtime.h>
#include <stdint.h>
#include <math.h>

#define BB 128
#define AA 8732
#define CC 21
#define MM 8
#define TT 512
#define NW (TT / 32)
#define CE_T 256                          // CE group threads (warps 0-7)
#define TROWS 512                         // rows per tile
#define NT 18                             // ceil(8732/512)
#define TILE_F4 (TROWS * CC / 4)          // 2688 float4 per full tile
#define TILE_B  (TROWS * CC * 4)          // 43008 B

// dynamic smem layout
#define OFF_VAL  0                        // float s_val[8732]  (ce0)
#define OFF_IOU  34928                    // float s_iou[8732]
#define OFF_CLS  69856                    // uchar s_obj[8732] pad 8736
#define OFF_BUF  78592                    // 3 tile buffers
#define SMEM_TOTAL (OFF_BUF + 3 * TILE_B) // 207616 B

__device__ float g_pos[BB], g_hard[BB], g_loc[BB];
__device__ int   g_np[BB];
__device__ int   g_ctr = 0;

__device__ __forceinline__ void cp16(unsigned int dst, const void* src) {
    asm volatile("cp.async.cg.shared.global [%0], [%1], 16;" :: "r"(dst), "l"(src));
}
__device__ __forceinline__ void cp16_pred(unsigned int dst, const void* src, int ok) {
    asm volatile("{\n\t.reg .pred p;\n\tsetp.ne.s32 p, %2, 0;\n\t"
                 "@p cp.async.cg.shared.global [%0], [%1], 16;\n\t}"
                 :: "r"(dst), "l"(src), "r"(ok));
}
#define CP_COMMIT() asm volatile("cp.async.commit_group;" ::: "memory")
#define CP_WAIT2()  asm volatile("cp.async.wait_group 2;" ::: "memory")
#define BAR_CE()    asm volatile("bar.sync 1, 256;" ::: "memory")
#define BAR_MT()    asm volatile("bar.sync 2, 256;" ::: "memory")

// issue the cp.asyncs for one tile from the CE group (256 threads)
__device__ __forceinline__ void ce_prefetch(const char* dsm, const float4* sc4,
                                            int t, int ctid) {
    int rows = AA - t * TROWS; if (rows > TROWS) rows = TROWS;
    int n4 = (rows * CC) >> 2;
    const float4* src = sc4 + (size_t)t * TILE_F4;
    unsigned int dbase = (unsigned int)__cvta_generic_to_shared(
        (const void*)(dsm + OFF_BUF + (t % 3) * TILE_B));
    if (n4 == TILE_F4) {                       // full tile: unpredicated fast path
#pragma unroll
        for (int j = 0; j < 10; j++) {
            int i = ctid + j * CE_T;
            cp16(dbase + i * 16, (const void*)(src + i));
        }
        int i = ctid + 10 * CE_T;
        if (i < TILE_F4) cp16(dbase + i * 16, (const void*)(src + i));
    } else {
#pragma unroll
        for (int j = 0; j < 11; j++) {
            int i = ctid + j * CE_T;
            int ok = i < n4;
            cp16_pred(ok ? (dbase + i * 16) : dbase,
                      ok ? (const void*)(src + i) : (const void*)sc4, ok);
        }
    }
}

__global__ void __launch_bounds__(TT, 1) k_fused(
    const float* __restrict__ locs,
    const float* __restrict__ scores,
    const float* __restrict__ boxes,
    const int*   __restrict__ labels,
    const float* __restrict__ anchors,
    float* __restrict__ out)
{
    extern __shared__ char dsm[];
    float*         s_val = (float*)dsm;                       // ce0 per anchor
    float*         s_iou = (float*)(dsm + OFF_IOU);
    unsigned char* s_obj = (unsigned char*)(dsm + OFF_CLS);   // obj -> cls

    __shared__ float4 s_bx4[MM];
    __shared__ float4 s_raw4[MM];
    __shared__ float  s_area[MM];
    __shared__ int    s_lab[MM];
    __shared__ float  s_wv[8][MM];
    __shared__ int    s_wi[8][MM];
    __shared__ int    s_afo[MM];
    __shared__ float  s_redf[NW];
    __shared__ float  s_redf2[NW];
    __shared__ int    s_redi[NW];
    __shared__ unsigned s_cnt[2][NW];
    __shared__ int    s_npos;
    __shared__ float  s_lsum, s_cpos;
    __shared__ int    s_bin1;  __shared__ unsigned s_chi;
    __shared__ unsigned s_prefix;
    __shared__ int    s_ticket;

    const int b = blockIdx.x, tid = threadIdx.x;
    const int lane = tid & 31, wid = tid >> 5;
    const float4* anc4 = (const float4*)anchors;
    const float*  scb  = scores + (size_t)b * AA * CC;
    const float4* sc4  = (const float4*)scb;

    if (tid < CE_T) {
        // ================== CE streaming group (warps 0-7) ==================
        const int ctid = tid;
#pragma unroll
        for (int t = 0; t < 3; t++) { ce_prefetch(dsm, sc4, t, ctid); CP_COMMIT(); }

        for (int t = 0; t < NT; t++) {
            CP_WAIT2();
            BAR_CE();
            const float* buf = (const float*)(dsm + OFF_BUF + (t % 3) * TILE_B);
            int rows = AA - t * TROWS; if (rows > TROWS) rows = TROWS;
            int r0 = ctid, r1 = ctid + CE_T;
            int a0 = r0 < rows, a1 = r1 < rows;
            const float* x0 = buf + (a0 ? r0 * CC : 0);
            const float* x1 = buf + (a1 ? r1 * CC : 0);
            // two interleaved rows: 6 independent accumulator chains
            float p0 = 0.f, p1 = 0.f, p2 = 0.f;
            float q0 = 0.f, q1 = 0.f, q2 = 0.f;
#pragma unroll
            for (int c = 0; c < CC; c += 3) {
                p0 += __expf(x0[c]);
                q0 += __expf(x1[c]);
                if (c + 1 < CC) { p1 += __expf(x0[c + 1]); q1 += __expf(x1[c + 1]); }
                if (c + 2 < CC) { p2 += __expf(x0[c + 2]); q2 += __expf(x1[c + 2]); }
            }
            float ce0 = __logf(p0 + p1 + p2) - x0[0];
            float ce1 = __logf(q0 + q1 + q2) - x1[0];
            if (a0) s_val[t * TROWS + r0] = ce0;
            if (a1) s_val[t * TROWS + r1] = ce1;
            BAR_CE();                          // reads of buffer (t%3) done
            int tn = t + 3;
            if (tn < NT) ce_prefetch(dsm, sc4, tn, ctid);
            CP_COMMIT();
        }
    } else {
        // ================== matching group (warps 8-15) ==================
        const int mtid = tid - CE_T;            // 0..255
        const int mwid = mtid >> 5;             // 0..7
        if (mtid < MM) {
            int m = mtid;
            float x1 = boxes[(b * MM + m) * 4 + 0];
            float y1 = boxes[(b * MM + m) * 4 + 1];
            float x2 = boxes[(b * MM + m) * 4 + 2];
            float y2 = boxes[(b * MM + m) * 4 + 3];
            s_raw4[m] = make_float4(x1, y1, x2, y2);
            float sx1 = x1 / 300.f, sy1 = y1 / 300.f, sx2 = x2 / 300.f, sy2 = y2 / 300.f;
            s_bx4[m] = make_float4(sx1, sy1, sx2, sy2);
            s_area[m] = (sx2 - sx1) * (sy2 - sy1);
            s_lab[m]  = labels[b * MM + m];
        }
        BAR_MT();

        float bestv[MM]; int besti[MM];
#pragma unroll
        for (int m = 0; m < MM; m++) { bestv[m] = -1.f; besti[m] = 0; }

        // two anchors per iteration; tree argmax (depth 3)
        for (int a = mtid; a < AA; a += 2 * CE_T) {
            int a2 = a + CE_T;
            int has2 = a2 < AA;

            float iouA[MM], iouB[MM];
            {
                float4 an = anc4[a];
                float ax1 = fmaf(an.z, -0.5f, an.x), ay1 = fmaf(an.w, -0.5f, an.y);
                float ax2 = fmaf(an.z,  0.5f, an.x), ay2 = fmaf(an.w,  0.5f, an.y);
                float areaA = (ax2 - ax1) * (ay2 - ay1);
#pragma unroll
                for (int m = 0; m < MM; m++) {
                    float4 bx = s_bx4[m];
                    float lx = fmaxf(bx.x, ax1), ly = fmaxf(bx.y, ay1);
                    float rx = fminf(bx.z, ax2), ry = fminf(bx.w, ay2);
                    float iw = fmaxf(rx - lx, 0.f), ih = fmaxf(ry - ly, 0.f);
                    float inter = iw * ih;
                    iouA[m] = __fdividef(inter, s_area[m] + areaA - inter);
                }
            }
            {
                float4 an = anc4[has2 ? a2 : a];
                float ax1 = fmaf(an.z, -0.5f, an.x), ay1 = fmaf(an.w, -0.5f, an.y);
                float ax2 = fmaf(an.z,  0.5f, an.x), ay2 = fmaf(an.w,  0.5f, an.y);
                float areaA = (ax2 - ax1) * (ay2 - ay1);
#pragma unroll
                for (int m = 0; m < MM; m++) {
                    float4 bx = s_bx4[m];
                    float lx = fmaxf(bx.x, ax1), ly = fmaxf(bx.y, ay1);
                    float rx = fminf(bx.z, ax2), ry = fminf(bx.w, ay2);
                    float iw = fmaxf(rx - lx, 0.f), ih = fmaxf(ry - ly, 0.f);
                    float inter = iw * ih;
                    iouB[m] = has2 ? __fdividef(inter, s_area[m] + areaA - inter) : -1.f;
                }
            }
            // per-object running argmax (first index on tie: strict >)
#pragma unroll
            for (int m = 0; m < MM; m++) {
                if (iouA[m] > bestv[m]) { bestv[m] = iouA[m]; besti[m] = a; }
                if (iouB[m] > bestv[m]) { bestv[m] = iouB[m]; besti[m] = a2; }
            }
            // tree argmax over m, first-index tie-break (strict > to replace)
            {
                int i01 = (iouA[1] > iouA[0]) ? 1 : 0; float v01 = fmaxf(iouA[0], iouA[1]);
                int i23 = (iouA[3] > iouA[2]) ? 3 : 2; float v23 = fmaxf(iouA[2], iouA[3]);
                int i45 = (iouA[5] > iouA[4]) ? 5 : 4; float v45 = fmaxf(iouA[4], iouA[5]);
                int i67 = (iouA[7] > iouA[6]) ? 7 : 6; float v67 = fmaxf(iouA[6], iouA[7]);
                int i03 = (v23 > v01) ? i23 : i01;     float v03 = fmaxf(v01, v23);
                int i47 = (v67 > v45) ? i67 : i45;     float v47 = fmaxf(v45, v67);
                int i07 = (v47 > v03) ? i47 : i03;     float v07 = fmaxf(v03, v47);
                s_iou[a] = v07;
                s_obj[a] = (unsigned char)i07;
            }
            if (has2) {
                int i01 = (iouB[1] > iouB[0]) ? 1 : 0; float v01 = fmaxf(iouB[0], iouB[1]);
                int i23 = (iouB[3] > iouB[2]) ? 3 : 2; float v23 = fmaxf(iouB[2], iouB[3]);
                int i45 = (iouB[5] > iouB[4]) ? 5 : 4; float v45 = fmaxf(iouB[4], iouB[5]);
                int i67 = (iouB[7] > iouB[6]) ? 7 : 6; float v67 = fmaxf(iouB[6], iouB[7]);
                int i03 = (v23 > v01) ? i23 : i01;     float v03 = fmaxf(v01, v23);
                int i47 = (v67 > v45) ? i67 : i45;     float v47 = fmaxf(v45, v67);
                int i07 = (v47 > v03) ? i47 : i03;     float v07 = fmaxf(v03, v47);
                s_iou[a2] = v07;
                s_obj[a2] = (unsigned char)i07;
            }
        }

#pragma unroll
        for (int m = 0; m < MM; m++) {
            float v = bestv[m]; int i = besti[m];
            for (int off = 16; off; off >>= 1) {
                float ov = __shfl_down_sync(0xffffffffu, v, off);
                int   oi = __shfl_down_sync(0xffffffffu, i, off);
                if (ov > v || (ov == v && oi < i)) { v = ov; i = oi; }
            }
            if (lane == 0) { s_wv[mwid][m] = v; s_wi[mwid][m] = i; }
        }
        BAR_MT();
        if (mtid < MM) {
            int m = mtid;
            float v = s_wv[0][m]; int i = s_wi[0][m];
            for (int w2 = 1; w2 < 8; w2++) {
                float ov = s_wv[w2][m]; int oi = s_wi[w2][m];
                if (ov > v || (ov == v && oi < i)) { v = ov; i = oi; }
            }
            s_afo[m] = i;
        }
        BAR_MT();
        if (mtid == 0) {       // sequential last-wins scatter override
            for (int m = 0; m < MM; m++) {
                int a = s_afo[m];
                s_obj[a] = (unsigned char)m;
                s_iou[a] = 1.0f;
            }
        }
    }

    __syncthreads();   // join: s_val (ce0), s_iou, s_obj complete

    // ---- phase B: labels + loc loss + positive-CE fixup ----
    {
        int npos = 0; float lsum = 0.f, cpos = 0.f;
        const float4* locs4 = (const float4*)locs + (size_t)b * AA;
        for (int a = tid; a < AA; a += TT) {
            float iou = s_iou[a];
            int   m   = s_obj[a];
            int   cls = (iou < 0.5f) ? 0 : s_lab[m];
            s_obj[a] = (unsigned char)cls;
            if (cls != 0) {
                npos++;
                float4 an = anc4[a];
                float4 rw = s_raw4[m];
                float t0 = (rw.x - an.x) * __fdividef(10.f, an.z);
                float t1 = (rw.y - an.y) * __fdividef(10.f, an.w);
                float t2 = __logf(__fdividef(rw.z, an.z)) * 5.f;
                float t3 = __logf(__fdividef(rw.w, an.w)) * 5.f;
                float4 p = locs4[a];
                lsum += fabsf(p.x - t0) + fabsf(p.y - t1) + fabsf(p.z - t2) + fabsf(p.w - t3);
                float x0 = scb[(size_t)a * CC];
                float xc = scb[(size_t)a * CC + cls];
                cpos += s_val[a] + x0 - xc;     // ce = ce0 + x[0] - x[cls]
                s_val[a] = 0.f;
            }
        }
        for (int off = 16; off; off >>= 1) {
            npos += __shfl_xor_sync(0xffffffffu, npos, off);
            lsum += __shfl_xor_sync(0xffffffffu, lsum, off);
            cpos += __shfl_xor_sync(0xffffffffu, cpos, off);
        }
        if (lane == 0) { s_redf[wid] = lsum; s_redf2[wid] = cpos; s_redi[wid] = npos; }
        __syncthreads();
        if (tid == 0) {
            float L = 0.f, P = 0.f; int N = 0;
            for (int w2 = 0; w2 < NW; w2++) { L += s_redf[w2]; P += s_redf2[w2]; N += s_redi[w2]; }
            s_npos = N; s_lsum = L; s_cpos = P;
        }
        __syncthreads();
    }

    // ---- phase D: top-k sum via 2-level histogram radix select ----
    {
        unsigned k = (unsigned)(3 * s_npos); if (k > AA) k = AA;
        unsigned* hist = (unsigned*)(dsm + OFF_BUF);

        for (int i = tid; i < 2048; i += TT) hist[i] = 0u;
        __syncthreads();
        for (int i = tid; i < AA; i += TT) {
            unsigned bin = __float_as_uint(s_val[i]) >> 20;
            unsigned mask  = __activemask();
            unsigned peers = __match_any_sync(mask, bin);
            int leader = __ffs(peers) - 1;
            if (lane == leader) atomicAdd(&hist[bin], (unsigned)__popc(peers));
        }
        __syncthreads();
        {
            int base = tid * 4;
            unsigned h0 = hist[base], h1 = hist[base + 1], h2 = hist[base + 2], h3 = hist[base + 3];
            unsigned loc = h0 + h1 + h2 + h3;
            unsigned inc = loc;
            for (int off = 1; off < 32; off <<= 1) {
                unsigned o = __shfl_down_sync(0xffffffffu, inc, off);
                if (lane < 32 - off) inc += o;
            }
            if (lane == 0) s_cnt[0][wid] = inc;
            __syncthreads();
            if (tid == 0) {
                unsigned c = 0;
                for (int w = NW - 1; w >= 0; --w) { s_cnt[1][w] = c; c += s_cnt[0][w]; }
            }
            __syncthreads();
            unsigned suf = s_cnt[1][wid] + (inc - loc);
            if (suf < k && suf + loc >= k) {
                unsigned c = suf;
                if      (c + h3 >= k) { s_bin1 = base + 3; s_chi = c; }
                else if (c + h3 + h2 >= k) { s_bin1 = base + 2; s_chi = c + h3; }
                else if (c + h3 + h2 + h1 >= k) { s_bin1 = base + 1; s_chi = c + h3 + h2; }
                else { s_bin1 = base; s_chi = c + h3 + h2 + h1; }
            }
        }
        __syncthreads();
        unsigned bin1 = (unsigned)s_bin1, chi = s_chi, k2 = k - chi;

        for (int i = tid; i < 4096; i += TT) hist[i] = 0u;
        __syncthreads();
        for (int i = tid; i < AA; i += TT) {
            unsigned u = __float_as_uint(s_val[i]);
            if ((u >> 20) == bin1) atomicAdd(&hist[(u >> 8) & 0xFFFu], 1u);
        }
        __syncthreads();
        {
            int base = tid * 8;
            unsigned h[8]; unsigned loc = 0;
#pragma unroll
            for (int j = 0; j < 8; j++) { h[j] = hist[base + j]; loc += h[j]; }
            unsigned inc = loc;
            for (int off = 1; off < 32; off <<= 1) {
                unsigned o = __shfl_down_sync(0xffffffffu, inc, off);
                if (lane < 32 - off) inc += o;
            }
            if (lane == 0) s_cnt[0][wid] = inc;
            __syncthreads();
            if (tid == 0) {
                unsigned c = 0;
                for (int w = NW - 1; w >= 0; --w) { s_cnt[1][w] = c; c += s_cnt[0][w]; }
            }
            __syncthreads();
            unsigned suf = s_cnt[1][wid] + (inc - loc);
            if (suf < k2 && suf + loc >= k2) {
                unsigned c = suf; int bin2 = base;
#pragma unroll
                for (int j = 7; j >= 0; --j) {
                    if (c + h[j] >= k2) { bin2 = base + j; break; }
                    c += h[j];
                }
                s_prefix = (bin1 << 20) | ((unsigned)bin2 << 8);
            }
        }
        __syncthreads();
        unsigned prefix = s_prefix;
        float kth = __uint_as_float(prefix);

        int cgt = 0; float sgt = 0.f;
        for (int i = tid; i < AA; i += TT) {
            float v = s_val[i];
            if (__float_as_uint(v) > prefix) { cgt++; sgt += v; }
        }
        for (int off = 16; off; off >>= 1) {
            cgt += __shfl_xor_sync(0xffffffffu, cgt, off);
            sgt += __shfl_xor_sync(0xffffffffu, sgt, off);
        }
        __syncthreads();
        if (lane == 0) { s_redi[wid] = cgt; s_redf[wid] = sgt; }
        __syncthreads();
        if (tid == 0) {
            int Cg = 0; float S = 0.f;
            for (int w2 = 0; w2 < NW; w2++) { Cg += s_redi[w2]; S += s_redf[w2]; }
            S += (float)((int)k - Cg) * kth;
            g_hard[b] = S;
            g_pos[b]  = s_cpos;
            g_loc[b]  = s_lsum;
            g_np[b]   = s_npos;
        }
    }

    // ---- phase E: last CTA reduces all per-image partials ----
    __threadfence();
    if (tid == 0) s_ticket = atomicAdd(&g_ctr, 1);
    __syncthreads();
    if (s_ticket == BB - 1) {
        __threadfence();
        if (tid == 0) g_ctr = 0;           // self-reset for next graph replay
        float p = 0.f, h = 0.f, l = 0.f; int n = 0;
        if (tid < BB) { p = g_pos[tid]; h = g_hard[tid]; l = g_loc[tid]; n = g_np[tid]; }
        for (int off = 16; off; off >>= 1) {
            p += __shfl_xor_sync(0xffffffffu, p, off);
            h += __shfl_xor_sync(0xffffffffu, h, off);
            l += __shfl_xor_sync(0xffffffffu, l, off);
            n += __shfl_xor_sync(0xffffffffu, n, off);
        }
        if (lane == 0) { s_redf[wid] = p + h; s_redf2[wid] = l; s_redi[wid] = n; }
        __syncthreads();
        if (tid == 0) {
            float PH = 0.f, L = 0.f; int N = 0;
            for (int w = 0; w < NW; w++) { PH += s_redf[w]; L += s_redf2[w]; N += s_redi[w]; }
            float np = (float)N;
            out[0] = PH / np + L / (np * 4.f);
        }
    }
}

extern "C" void kernel_launch(void* const* d_in, const int* in_sizes, int n_in,
                              void* d_out, int out_size) {
    const float* locs    = (const float*)d_in[0];
    const float* scores  = (const float*)d_in[1];
    const float* boxes   = (const float*)d_in[2];
    const int*   labels  = (const int*)d_in[3];
    const float* anchors = (const float*)d_in[4];
    float* out = (float*)d_out;

    cudaFuncSetAttribute(k_fused, cudaFuncAttributeMaxDynamicSharedMemorySize, SMEM_TOTAL);
    k_fused<<<BB, TT, SMEM_TOTAL>>>(locs, scores, boxes, labels, anchors, out);
}